// round 6
// baseline (speedup 1.0000x reference)
#include <cuda_runtime.h>
#include <cuda_fp16.h>
#include <cstdint>

// ============================================================================
// y[t, :] = weight[x[t], :] + A[x[t], :] @ B
//   tokens M = 16384, DIM N = 1024, RANK K = 256
// mma.sync.m16n8k16.f32.f16.f16.f32, 2 CTAs/SM, ldmatrix both operands,
// 3-stage cp.async pipeline (one barrier/chunk), L2-prefetched epilogue.
// ============================================================================
static constexpr int M_TOTAL = 16384;
static constexpr int DIM     = 1024;
static constexpr int RANK    = 256;

static constexpr int TILE_M  = 128;
static constexpr int TILE_N  = 128;
static constexpr int KC      = 64;              // K chunk (halves)
static constexpr int NCHUNK  = RANK / KC;       // 4
static constexpr int STAGES  = 3;

// Smem: pitch 72 halves (144 B) -> conflict-free ldmatrix (banks 4i mod 32)
static constexpr int PITCH        = 72;
static constexpr int TILE_HALVES  = 128 * PITCH;            // 9216 halves
static constexpr int TILE_BYTES_S = TILE_HALVES * 2;        // 18432 B
static constexpr int STAGE_BYTES  = 2 * TILE_BYTES_S;       // A + B per stage
static constexpr int SMEM_BYTES   = STAGES * STAGE_BYTES + 512;  // 111104 B

// Scratch: half B^T [DIM][RANK] (0.5 MB), gathered half A [M][RANK] (8 MB)
__device__ __half g_Bt[DIM * RANK];
__device__ __half g_Ah[M_TOTAL * RANK];

// ---------------------------------------------------------------------------
__device__ __forceinline__ uint32_t smem_to_u32(const void* p) {
    uint32_t a;
    asm("{ .reg .u64 t; cvta.to.shared.u64 t, %1; cvt.u32.u64 %0, t; }" : "=r"(a) : "l"(p));
    return a;
}
__device__ __forceinline__ void cp_async16(uint32_t dst, const void* src) {
    asm volatile("cp.async.cg.shared.global [%0], [%1], 16;" :: "r"(dst), "l"(src));
}
__device__ __forceinline__ void cp_commit() {
    asm volatile("cp.async.commit_group;" ::: "memory");
}
template <int N>
__device__ __forceinline__ void cp_wait() {
    asm volatile("cp.async.wait_group %0;" :: "n"(N) : "memory");
}
__device__ __forceinline__ void prefetch_l2(const void* p) {
    asm volatile("prefetch.global.L2 [%0];" :: "l"(p));
}
__device__ __forceinline__ void ldmatrix_x4(uint32_t& r0, uint32_t& r1,
                                            uint32_t& r2, uint32_t& r3, uint32_t addr) {
    asm volatile("ldmatrix.sync.aligned.m8n8.x4.shared.b16 {%0,%1,%2,%3}, [%4];"
                 : "=r"(r0), "=r"(r1), "=r"(r2), "=r"(r3) : "r"(addr));
}
__device__ __forceinline__ void mma_f16(float* c, const uint32_t* a, const uint32_t* b) {
    asm volatile(
        "mma.sync.aligned.m16n8k16.row.col.f32.f16.f16.f32 "
        "{%0,%1,%2,%3}, {%4,%5,%6,%7}, {%8,%9}, {%0,%1,%2,%3};\n"
        : "+f"(c[0]), "+f"(c[1]), "+f"(c[2]), "+f"(c[3])
        : "r"(a[0]), "r"(a[1]), "r"(a[2]), "r"(a[3]), "r"(b[0]), "r"(b[1]));
}

// ============================================================================
// Kernel 1 (fused prep):
//   blocks [0,256):     transpose+convert B -> g_Bt [DIM][RANK] half
//   blocks [256,2304):  gather+convert A rows: g_Ah[t] = half(A[x[t]]), 8 rows/blk
// ============================================================================
__global__ __launch_bounds__(256)
void prep_kernel(const int* __restrict__ x, const float* __restrict__ A,
                 const float* __restrict__ B) {
    if (blockIdx.x < 256) {
        __shared__ float t[32][33];
        const int n0 = (blockIdx.x & 31) * 32;
        const int k0 = (blockIdx.x >> 5) * 32;
        const int tx = threadIdx.x & 31;
        const int ty = threadIdx.x >> 5;
        #pragma unroll
        for (int j = 0; j < 32; j += 8)
            t[ty + j][tx] = B[(size_t)(k0 + ty + j) * DIM + n0 + tx];
        __syncthreads();
        #pragma unroll
        for (int j = 0; j < 32; j += 8)
            g_Bt[(size_t)(n0 + ty + j) * RANK + k0 + tx] = __float2half_rn(t[tx][ty + j]);
    } else {
        const int row  = (blockIdx.x - 256) * 8 + (threadIdx.x >> 5);
        const int lane = threadIdx.x & 31;
        const int tok  = x[row];
        const float4* src = (const float4*)(A + (size_t)tok * RANK) + lane * 2;
        float4 v0 = src[0], v1 = src[1];
        __half2 h[4];
        h[0] = __floats2half2_rn(v0.x, v0.y);
        h[1] = __floats2half2_rn(v0.z, v0.w);
        h[2] = __floats2half2_rn(v1.x, v1.y);
        h[3] = __floats2half2_rn(v1.z, v1.w);
        *(uint4*)(g_Ah + (size_t)row * RANK + lane * 8) = *(const uint4*)h;
    }
}

// ============================================================================
// Kernel 2: fused GEMM + weight-gather epilogue
//   grid: (8, 128) N fastest; block 256 = 8 warps; warp tile 64x32; 2 CTAs/SM
// ============================================================================
__global__ __launch_bounds__(256, 2)
void lora_embed_kernel(const int* __restrict__ x,
                       const float* __restrict__ weight,
                       float* __restrict__ out) {
    extern __shared__ __align__(16) char smem[];
    int* s_tok = (int*)(smem + STAGES * STAGE_BYTES);

    const int tid    = threadIdx.x;
    const int wid    = tid >> 5;
    const int lane   = tid & 31;
    const int group  = lane >> 2;   // 0..7
    const int tig    = lane & 3;    // 0..3
    const int warp_m = wid >> 2;    // 0..1
    const int warp_n = wid & 3;     // 0..3

    const int n0 = blockIdx.x * TILE_N;
    const int m0 = blockIdx.y * TILE_M;

    if (tid < 128) s_tok[tid] = x[m0 + tid];

    const uint32_t sb = smem_to_u32(smem);

    // Loader mapping: 2 threads per row, each covers 32 halves (4x16B) / chunk
    const int lrow  = tid >> 1;
    const int lhalf = tid & 1;
    const __half* a_src = g_Ah + (size_t)(m0 + lrow) * RANK + lhalf * 32;
    const __half* b_src = g_Bt + (size_t)(n0 + lrow) * RANK + lhalf * 32;
    const uint32_t a_dst = sb + (lrow * PITCH + lhalf * 32) * 2;
    const uint32_t b_dst = a_dst + TILE_BYTES_S;

    // L2-prefetch this CTA's epilogue weight slice (64KB): 2 lines per thread.
    {
        const int ptok = x[m0 + lrow];
        const float* pw = weight + (size_t)ptok * DIM + n0 + lhalf * 64;
        prefetch_l2(pw);
        prefetch_l2(pw + 32);
    }

    auto prefetch = [&](int c) {
        const uint32_t soff = (uint32_t)(c % STAGES) * STAGE_BYTES;
        #pragma unroll
        for (int i = 0; i < 4; i++) {
            cp_async16(a_dst + soff + i * 16, a_src + c * KC + i * 8);
            cp_async16(b_dst + soff + i * 16, b_src + c * KC + i * 8);
        }
        cp_commit();
    };

    float acc[4][4][4];
    #pragma unroll
    for (int mt = 0; mt < 4; mt++)
        #pragma unroll
        for (int nt = 0; nt < 4; nt++)
            #pragma unroll
            for (int r = 0; r < 4; r++) acc[mt][nt][r] = 0.f;

    // A ldmatrix lane offset: row = warp_m*64 + (lane&15), koff = (lane>>4)*8
    const uint32_t a_lane_off =
        (uint32_t)(((warp_m * 64 + (lane & 15)) * PITCH + (lane >> 4) * 8) * 2);
    // B ldmatrix lane offset (x4 = mats [nlo klo, nlo khi, nhi klo, nhi khi])
    const uint32_t b_lane_off =
        (uint32_t)(((warp_n * 32 + ((lane >> 4) << 3) + (lane & 7)) * PITCH
                    + ((lane >> 3) & 1) * 8) * 2);

    auto compute = [&](int c) {
        const uint32_t abuf = sb + (uint32_t)(c % STAGES) * STAGE_BYTES;
        const uint32_t bbuf = abuf + (uint32_t)TILE_BYTES_S;
        #pragma unroll
        for (int ks = 0; ks < 4; ks++) {
            const uint32_t k0b = (uint32_t)(ks * 16 * 2);
            uint32_t af[4][4];
            #pragma unroll
            for (int mt = 0; mt < 4; mt++)
                ldmatrix_x4(af[mt][0], af[mt][1], af[mt][2], af[mt][3],
                            abuf + a_lane_off + (uint32_t)(mt * 16 * PITCH * 2) + k0b);
            uint32_t bf[4][2];
            #pragma unroll
            for (int q = 0; q < 2; q++)
                ldmatrix_x4(bf[2 * q][0], bf[2 * q][1], bf[2 * q + 1][0], bf[2 * q + 1][1],
                            bbuf + b_lane_off + (uint32_t)(q * 16 * PITCH * 2) + k0b);
            #pragma unroll
            for (int mt = 0; mt < 4; mt++)
                #pragma unroll
                for (int nt = 0; nt < 4; nt++)
                    mma_f16(acc[mt][nt], af[mt], bf[nt]);
        }
    };

    // 3-stage pipeline over NCHUNK=4 chunks, one barrier per chunk.
    // prefetch(c+2) after sync(c) is safe: it writes buf (c+2)%3 == (c-1)%3,
    // whose consumers (compute(c-1)) all passed sync(c).
    prefetch(0);
    prefetch(1);

    cp_wait<1>(); __syncthreads(); prefetch(2); compute(0);
    cp_wait<1>(); __syncthreads(); prefetch(3); compute(1);
    cp_wait<1>(); __syncthreads();              compute(2);
    cp_wait<0>(); __syncthreads();              compute(3);

    // Epilogue: out = weight[tok] + acc  (weight slice is L2-hot by now)
    #pragma unroll
    for (int mt = 0; mt < 4; mt++) {
        #pragma unroll
        for (int mo = 0; mo < 2; mo++) {
            const int row = warp_m * 64 + mt * 16 + mo * 8 + group;
            const int tok = s_tok[row];
            const float* wrow = weight + (size_t)tok * DIM + n0;
            float* orow = out + (size_t)(m0 + row) * DIM + n0;
            #pragma unroll
            for (int nt = 0; nt < 4; nt++) {
                const int col = warp_n * 32 + nt * 8 + tig * 2;
                float2 w = *(const float2*)(wrow + col);
                float2 o;
                o.x = w.x + acc[mt][nt][mo * 2 + 0];
                o.y = w.y + acc[mt][nt][mo * 2 + 1];
                *(float2*)(orow + col) = o;
            }
        }
    }
}

// ============================================================================
// Launch
// ============================================================================
extern "C" void kernel_launch(void* const* d_in, const int* in_sizes, int n_in,
                              void* d_out, int out_size) {
    const int*   x      = (const int*)d_in[0];       // [16384] int32
    const float* weight = (const float*)d_in[1];     // [128000, 1024]
    const float* A      = (const float*)d_in[2];     // [128000, 256]
    const float* B      = (const float*)d_in[3];     // [256, 1024]
    float* out          = (float*)d_out;             // [16384, 1024]

    (void)in_sizes; (void)n_in; (void)out_size;

    // Fused prep: 256 transpose blocks + 2048 gather blocks
    prep_kernel<<<256 + M_TOTAL / 8, 256>>>(x, A, B);

    {
        static bool attr_set = false;
        if (!attr_set) {
            cudaFuncSetAttribute(lora_embed_kernel,
                                 cudaFuncAttributeMaxDynamicSharedMemorySize, SMEM_BYTES);
            attr_set = true;
        }
        dim3 grid(DIM / TILE_N, M_TOTAL / TILE_M);   // (8, 128) — N fastest
        lora_embed_kernel<<<grid, 256, SMEM_BYTES>>>(x, weight, out);
    }
}

// round 7
// speedup vs baseline: 1.3606x; 1.3606x over previous
#include <cuda_runtime.h>
#include <cuda_fp16.h>
#include <cstdint>

// ============================================================================
// y[t, :] = weight[x[t], :] + A[x[t], :] @ B
//   tokens M = 16384, DIM N = 1024, RANK K = 256
// mma.sync.m16n8k16.f32.f16.f16.f32, 2 CTAs/SM, ldmatrix both operands,
// 3-stage cp.async pipeline; epilogue weight rows cp.async-staged into the
// dead pipeline buffers, overlapped with the last two K chunks.
// ============================================================================
static constexpr int M_TOTAL = 16384;
static constexpr int DIM     = 1024;
static constexpr int RANK    = 256;

static constexpr int TILE_M  = 128;
static constexpr int TILE_N  = 128;
static constexpr int KC      = 64;              // K chunk (halves)
static constexpr int NCHUNK  = RANK / KC;       // 4
static constexpr int STAGES  = 3;

// Smem: pitch 72 halves (144 B) -> conflict-free ldmatrix (banks 4i mod 32)
static constexpr int PITCH        = 72;
static constexpr int TILE_HALVES  = 128 * PITCH;            // 9216 halves
static constexpr int TILE_BYTES_S = TILE_HALVES * 2;        // 18432 B
static constexpr int STAGE_BYTES  = 2 * TILE_BYTES_S;       // A + B per stage
static constexpr int SMEM_BYTES   = STAGES * STAGE_BYTES + 512;  // 111104 B

// Weight staging: 64 rows x 528 B (132 floats, 16B-aligned pitch) = 33792 B
// fits in one 36864 B stage buffer.
static constexpr int W_PITCH_F = 132;
static constexpr int W_PITCH_B = 528;

// Scratch: half B^T [DIM][RANK] (0.5 MB), gathered half A [M][RANK] (8 MB)
__device__ __half g_Bt[DIM * RANK];
__device__ __half g_Ah[M_TOTAL * RANK];

// ---------------------------------------------------------------------------
__device__ __forceinline__ uint32_t smem_to_u32(const void* p) {
    uint32_t a;
    asm("{ .reg .u64 t; cvta.to.shared.u64 t, %1; cvt.u32.u64 %0, t; }" : "=r"(a) : "l"(p));
    return a;
}
__device__ __forceinline__ void cp_async16(uint32_t dst, const void* src) {
    asm volatile("cp.async.cg.shared.global [%0], [%1], 16;" :: "r"(dst), "l"(src));
}
__device__ __forceinline__ void cp_commit() {
    asm volatile("cp.async.commit_group;" ::: "memory");
}
template <int N>
__device__ __forceinline__ void cp_wait() {
    asm volatile("cp.async.wait_group %0;" :: "n"(N) : "memory");
}
__device__ __forceinline__ void ldmatrix_x4(uint32_t& r0, uint32_t& r1,
                                            uint32_t& r2, uint32_t& r3, uint32_t addr) {
    asm volatile("ldmatrix.sync.aligned.m8n8.x4.shared.b16 {%0,%1,%2,%3}, [%4];"
                 : "=r"(r0), "=r"(r1), "=r"(r2), "=r"(r3) : "r"(addr));
}
__device__ __forceinline__ void mma_f16(float* c, const uint32_t* a, const uint32_t* b) {
    asm volatile(
        "mma.sync.aligned.m16n8k16.row.col.f32.f16.f16.f32 "
        "{%0,%1,%2,%3}, {%4,%5,%6,%7}, {%8,%9}, {%0,%1,%2,%3};\n"
        : "+f"(c[0]), "+f"(c[1]), "+f"(c[2]), "+f"(c[3])
        : "r"(a[0]), "r"(a[1]), "r"(a[2]), "r"(a[3]), "r"(b[0]), "r"(b[1]));
}

// ============================================================================
// Kernel 1 (fused prep):
//   blocks [0,256):     transpose+convert B -> g_Bt [DIM][RANK] half
//   blocks [256,2304):  gather+convert A rows: g_Ah[t] = half(A[x[t]]), 8 rows/blk
// ============================================================================
__global__ __launch_bounds__(256)
void prep_kernel(const int* __restrict__ x, const float* __restrict__ A,
                 const float* __restrict__ B) {
    if (blockIdx.x < 256) {
        __shared__ float t[32][33];
        const int n0 = (blockIdx.x & 31) * 32;
        const int k0 = (blockIdx.x >> 5) * 32;
        const int tx = threadIdx.x & 31;
        const int ty = threadIdx.x >> 5;
        #pragma unroll
        for (int j = 0; j < 32; j += 8)
            t[ty + j][tx] = B[(size_t)(k0 + ty + j) * DIM + n0 + tx];
        __syncthreads();
        #pragma unroll
        for (int j = 0; j < 32; j += 8)
            g_Bt[(size_t)(n0 + ty + j) * RANK + k0 + tx] = __float2half_rn(t[tx][ty + j]);
    } else {
        const int row  = (blockIdx.x - 256) * 8 + (threadIdx.x >> 5);
        const int lane = threadIdx.x & 31;
        const int tok  = x[row];
        const float4* src = (const float4*)(A + (size_t)tok * RANK) + lane * 2;
        float4 v0 = src[0], v1 = src[1];
        __half2 h[4];
        h[0] = __floats2half2_rn(v0.x, v0.y);
        h[1] = __floats2half2_rn(v0.z, v0.w);
        h[2] = __floats2half2_rn(v1.x, v1.y);
        h[3] = __floats2half2_rn(v1.z, v1.w);
        *(uint4*)(g_Ah + (size_t)row * RANK + lane * 8) = *(const uint4*)h;
    }
}

// ============================================================================
// Kernel 2: fused GEMM + weight-gather epilogue
//   grid: (8, 128) N fastest; block 256 = 8 warps; warp tile 64x32; 2 CTAs/SM
// ============================================================================
__global__ __launch_bounds__(256, 2)
void lora_embed_kernel(const int* __restrict__ x,
                       const float* __restrict__ weight,
                       float* __restrict__ out) {
    extern __shared__ __align__(16) char smem[];
    int* s_tok = (int*)(smem + STAGES * STAGE_BYTES);

    const int tid    = threadIdx.x;
    const int wid    = tid >> 5;
    const int lane   = tid & 31;
    const int group  = lane >> 2;   // 0..7
    const int tig    = lane & 3;    // 0..3
    const int warp_m = wid >> 2;    // 0..1
    const int warp_n = wid & 3;     // 0..3

    const int n0 = blockIdx.x * TILE_N;
    const int m0 = blockIdx.y * TILE_M;

    if (tid < 128) s_tok[tid] = x[m0 + tid];

    const uint32_t sb = smem_to_u32(smem);

    // Loader mapping: 2 threads per row, each covers 32 halves (4x16B) / chunk
    const int lrow  = tid >> 1;
    const int lhalf = tid & 1;
    const __half* a_src = g_Ah + (size_t)(m0 + lrow) * RANK + lhalf * 32;
    const __half* b_src = g_Bt + (size_t)(n0 + lrow) * RANK + lhalf * 32;
    const uint32_t a_dst = sb + (lrow * PITCH + lhalf * 32) * 2;
    const uint32_t b_dst = a_dst + TILE_BYTES_S;

    auto prefetch = [&](int c) {
        const uint32_t soff = (uint32_t)(c % STAGES) * STAGE_BYTES;
        #pragma unroll
        for (int i = 0; i < 4; i++) {
            cp_async16(a_dst + soff + i * 16, a_src + c * KC + i * 8);
            cp_async16(b_dst + soff + i * 16, b_src + c * KC + i * 8);
        }
        cp_commit();
    };

    // Stage 64 weight rows (half h of the M-tile) into dead pipeline buffer
    // (1 + h). Layout: row-major, pitch 528 B. 256 threads x 8 cp.async(16B).
    auto stage_weight = [&](int h) {
        const uint32_t dsm = sb + (uint32_t)(1 + h) * STAGE_BYTES;
        #pragma unroll
        for (int i = 0; i < 8; i++) {
            const int idx = tid + 256 * i;        // 0..2047
            const int row = idx >> 5;             // 0..63
            const int c16 = idx & 31;             // 16B chunk within 512B row
            const int tok = s_tok[h * 64 + row];
            cp_async16(dsm + (uint32_t)(row * W_PITCH_B + c16 * 16),
                       weight + (size_t)tok * DIM + n0 + c16 * 4);
        }
        cp_commit();
    };

    float acc[4][4][4];
    #pragma unroll
    for (int mt = 0; mt < 4; mt++)
        #pragma unroll
        for (int nt = 0; nt < 4; nt++)
            #pragma unroll
            for (int r = 0; r < 4; r++) acc[mt][nt][r] = 0.f;

    // A ldmatrix lane offset: row = warp_m*64 + (lane&15), koff = (lane>>4)*8
    const uint32_t a_lane_off =
        (uint32_t)(((warp_m * 64 + (lane & 15)) * PITCH + (lane >> 4) * 8) * 2);
    // B ldmatrix lane offset (x4 = mats [nlo klo, nlo khi, nhi klo, nhi khi])
    const uint32_t b_lane_off =
        (uint32_t)(((warp_n * 32 + ((lane >> 4) << 3) + (lane & 7)) * PITCH
                    + ((lane >> 3) & 1) * 8) * 2);

    auto compute = [&](int c) {
        const uint32_t abuf = sb + (uint32_t)(c % STAGES) * STAGE_BYTES;
        const uint32_t bbuf = abuf + (uint32_t)TILE_BYTES_S;
        #pragma unroll
        for (int ks = 0; ks < 4; ks++) {
            const uint32_t k0b = (uint32_t)(ks * 16 * 2);
            uint32_t af[4][4];
            #pragma unroll
            for (int mt = 0; mt < 4; mt++)
                ldmatrix_x4(af[mt][0], af[mt][1], af[mt][2], af[mt][3],
                            abuf + a_lane_off + (uint32_t)(mt * 16 * PITCH * 2) + k0b);
            uint32_t bf[4][2];
            #pragma unroll
            for (int q = 0; q < 2; q++)
                ldmatrix_x4(bf[2 * q][0], bf[2 * q][1], bf[2 * q + 1][0], bf[2 * q + 1][1],
                            bbuf + b_lane_off + (uint32_t)(q * 16 * PITCH * 2) + k0b);
            #pragma unroll
            for (int mt = 0; mt < 4; mt++)
                #pragma unroll
                for (int nt = 0; nt < 4; nt++)
                    mma_f16(acc[mt][nt], af[mt], bf[nt]);
        }
    };

    // Pipeline (NCHUNK=4, 3 stages). Commit-group order:
    //   G0=pf0 G1=pf1 G2=pf2 G3=pf3 G4=weight(h=0) G5=weight(h=1)
    // wait<1> before compute(2) ensures G2 (outstanding: G2,G3);
    // wait<1> before compute(3) ensures G3 (outstanding: G3,G4).
    // Buffer safety: stage_weight(0) writes buf1 after ALL warps passed the
    // barrier following compute(1)'s wait (done reading buf1); stage_weight(1)
    // writes buf2 after the barrier following compute(2). compute(3) uses buf0.
    prefetch(0);
    prefetch(1);

    cp_wait<1>(); __syncthreads(); prefetch(2);        compute(0);
    cp_wait<1>(); __syncthreads(); prefetch(3);        compute(1);
    cp_wait<1>(); __syncthreads(); stage_weight(0);    compute(2);
    cp_wait<1>(); __syncthreads(); stage_weight(1);    compute(3);
    cp_wait<0>(); __syncthreads();   // weight halves resident in smem

    // Epilogue: out = weight_smem + acc. warp_m selects the staged half.
    const float* wsm = (const float*)(smem + (size_t)(1 + warp_m) * STAGE_BYTES);
    #pragma unroll
    for (int mt = 0; mt < 4; mt++) {
        #pragma unroll
        for (int mo = 0; mo < 2; mo++) {
            const int r = mt * 16 + mo * 8 + group;           // 0..63 in half
            const float* wrow = wsm + r * W_PITCH_F;
            float* orow = out + (size_t)(m0 + warp_m * 64 + r) * DIM + n0;
            #pragma unroll
            for (int nt = 0; nt < 4; nt++) {
                const int col = warp_n * 32 + nt * 8 + tig * 2;
                float2 w = *(const float2*)(wrow + col);
                float2 o;
                o.x = w.x + acc[mt][nt][mo * 2 + 0];
                o.y = w.y + acc[mt][nt][mo * 2 + 1];
                *(float2*)(orow + col) = o;
            }
        }
    }
}

// ============================================================================
// Launch
// ============================================================================
extern "C" void kernel_launch(void* const* d_in, const int* in_sizes, int n_in,
                              void* d_out, int out_size) {
    const int*   x      = (const int*)d_in[0];       // [16384] int32
    const float* weight = (const float*)d_in[1];     // [128000, 1024]
    const float* A      = (const float*)d_in[2];     // [128000, 256]
    const float* B      = (const float*)d_in[3];     // [256, 1024]
    float* out          = (float*)d_out;             // [16384, 1024]

    (void)in_sizes; (void)n_in; (void)out_size;

    // Fused prep: 256 transpose blocks + 2048 gather blocks
    prep_kernel<<<256 + M_TOTAL / 8, 256>>>(x, A, B);

    {
        static bool attr_set = false;
        if (!attr_set) {
            cudaFuncSetAttribute(lora_embed_kernel,
                                 cudaFuncAttributeMaxDynamicSharedMemorySize, SMEM_BYTES);
            attr_set = true;
        }
        dim3 grid(DIM / TILE_N, M_TOTAL / TILE_M);   // (8, 128) — N fastest
        lora_embed_kernel<<<grid, 256, SMEM_BYTES>>>(x, weight, out);
    }
}